// round 10
// baseline (speedup 1.0000x reference)
#include <cuda_runtime.h>

#define SEQ 1024
#define NB  48
#define NROWS (NB * SEQ)            // 49152 rows, 9 channels
#define NBLK_A 1152                  // 3 attns * 48 batches * 8 row-chunks
#define TPB_A 256

typedef unsigned long long ull;

// scratch (allocation-free rule: __device__ globals)
__device__ float g_att[9 * NROWS];      // SoA: [channel][row]
__device__ float g_part[NBLK_A * 6];    // per-block partial sum/sumsq (3 ch)
__device__ float g_ss[18];              // BN scale[9], shift[9]

// ---------------- packed f32x2 helpers (Blackwell) ----------------
__device__ __forceinline__ ull pack2(float lo, float hi) {
    ull r; asm("mov.b64 %0, {%1, %2};" : "=l"(r) : "f"(lo), "f"(hi)); return r;
}
__device__ __forceinline__ void unpack2(ull v, float& lo, float& hi) {
    asm("mov.b64 {%0, %1}, %2;" : "=f"(lo), "=f"(hi) : "l"(v));
}
__device__ __forceinline__ ull fma2(ull a, ull b, ull c) {
    ull d; asm("fma.rn.f32x2 %0, %1, %2, %3;" : "=l"(d) : "l"(a), "l"(b), "l"(c)); return d;
}
__device__ __forceinline__ ull mul2(ull a, ull b) {
    ull d; asm("mul.rn.f32x2 %0, %1, %2;" : "=l"(d) : "l"(a), "l"(b)); return d;
}
__device__ __forceinline__ ull add2(ull a, ull b) {
    ull d; asm("add.rn.f32x2 %0, %1, %2;" : "=l"(d) : "l"(a), "l"(b)); return d;
}
__device__ __forceinline__ float ex2f(float d) {
    float e; asm("ex2.approx.f32 %0, %1;" : "=f"(e) : "f"(d)); return e;
}
__device__ __forceinline__ ull ex2p(ull d) {
    float lo, hi; unpack2(d, lo, hi);
    return pack2(ex2f(lo), ex2f(hi));
}

// ---------------------------------------------------------------------------
// Kernel A: fused projection + cross attention + BN partials.
// block = (attn, batch, 128-row chunk); 256 threads = 8 warps.
// warp: tq = warp&3 (t-quarter, 256 t), rg = warp>>2 (row group).
// thread: 2 rows x 256 t, packed f32x2 over t-pairs.
// NEW: 1 of 4 packed exps per group computed on the FMA/ALU pipes
// (Schraudolph-refined exp2, deg-4 poly) to offload the saturated MUFU.
// ---------------------------------------------------------------------------
__global__ __launch_bounds__(TPB_A, 3) void attn_kernel(
    const float* __restrict__ x,
    const float* __restrict__ WQ, const float* __restrict__ bQ,
    const float* __restrict__ WK, const float* __restrict__ bK,
    const float* __restrict__ WV, const float* __restrict__ bV)
{
    __shared__ __align__(16) float KV[SEQ / 4 * 24];   // 24 KB interleaved
    __shared__ __align__(16) float4 cbuf[3][64][2];    // quarter 1..3 partials
    __shared__ float sred[8 * 6];

    const int blk  = blockIdx.x;
    const int attn = blk / (NB * 8);
    const int rem  = blk - attn * (NB * 8);
    const int b    = rem >> 3;
    const int rc   = rem & 7;           // 128-row chunk of the batch

    // a1=attn(Q2,K0,V1), a2=attn(Q0,K1,V2), a3=attn(Q1,K2,V0)
    const int qmap[3] = {2, 0, 1};
    const int vmap[3] = {1, 2, 0};
    const int qb = qmap[attn], kb = attn, vb = vmap[attn];

    const int tid  = threadIdx.x;
    const int warp = tid >> 5;
    const int lane = tid & 31;
    const int tq   = warp & 3;           // t-quarter this warp sums
    const int rg   = warp >> 2;          // row group (0/1)
    const int slot = rg * 32 + lane;     // 0..63

    // ---- phase 1: K,V tiles (3x3 projection), interleaved layout ----
    {
        const float* wk = WK + kb * 9;  const float* bk = bK + kb * 3;
        const float* wv = WV + vb * 9;  const float* bv = bV + vb * 3;
        #pragma unroll
        for (int it = 0; it < SEQ / TPB_A; ++it) {
            int t = tid + it * TPB_A;
            float* grp = KV + (t >> 2) * 24 + (t & 3);
            const float* xk = x + ((size_t)(kb * NB + b) * SEQ + t) * 3;
            float x0 = xk[0], x1 = xk[1], x2 = xk[2];
            grp[0]  = fmaf(wk[0], x0, fmaf(wk[1], x1, fmaf(wk[2], x2, bk[0])));
            grp[4]  = fmaf(wk[3], x0, fmaf(wk[4], x1, fmaf(wk[5], x2, bk[1])));
            grp[8]  = fmaf(wk[6], x0, fmaf(wk[7], x1, fmaf(wk[8], x2, bk[2])));

            const float* xv = x + ((size_t)(vb * NB + b) * SEQ + t) * 3;
            float y0 = xv[0], y1 = xv[1], y2 = xv[2];
            grp[12] = fmaf(wv[0], y0, fmaf(wv[1], y1, fmaf(wv[2], y2, bv[0])));
            grp[16] = fmaf(wv[3], y0, fmaf(wv[4], y1, fmaf(wv[5], y2, bv[1])));
            grp[20] = fmaf(wv[6], y0, fmaf(wv[7], y1, fmaf(wv[8], y2, bv[2])));
        }
    }
    __syncthreads();

    // ---- per-thread Q for rows r0 = rc*128 + slot, r1 = r0 + 64 ----
    const float qscale = 1.4426950408889634f / 1.7320508075688772f;
    ull q0x, q0y, q0z, q1x, q1y, q1z;
    {
        const float* wq = WQ + qb * 9;  const float* bq = bQ + qb * 3;
        const int rbase = rc * 128;
        const float* xq = x + ((size_t)(qb * NB + b) * SEQ + rbase + slot) * 3;
        float x0 = xq[0], x1 = xq[1], x2 = xq[2];
        float a = fmaf(wq[0], x0, fmaf(wq[1], x1, fmaf(wq[2], x2, bq[0]))) * qscale;
        float c = fmaf(wq[3], x0, fmaf(wq[4], x1, fmaf(wq[5], x2, bq[1]))) * qscale;
        float d = fmaf(wq[6], x0, fmaf(wq[7], x1, fmaf(wq[8], x2, bq[2]))) * qscale;
        q0x = pack2(a, a); q0y = pack2(c, c); q0z = pack2(d, d);
        xq = x + ((size_t)(qb * NB + b) * SEQ + rbase + slot + 64) * 3;
        x0 = xq[0]; x1 = xq[1]; x2 = xq[2];
        a = fmaf(wq[0], x0, fmaf(wq[1], x1, fmaf(wq[2], x2, bq[0]))) * qscale;
        c = fmaf(wq[3], x0, fmaf(wq[4], x1, fmaf(wq[5], x2, bq[1]))) * qscale;
        d = fmaf(wq[6], x0, fmaf(wq[7], x1, fmaf(wq[8], x2, bq[2]))) * qscale;
        q1x = pack2(a, a); q1y = pack2(c, c); q1z = pack2(d, d);
    }

    // packed constants for the FMA-pipe exp2 (live across the loop)
    const ull CR  = pack2( 12582912.0f,  12582912.0f);   // 1.5 * 2^23
    const ull CNR = pack2(-12582912.0f, -12582912.0f);
    const ull CN1 = pack2(-1.0f, -1.0f);
    const ull PC1 = pack2(0.69314718056f, 0.69314718056f);
    const ull PC2 = pack2(0.24022650696f, 0.24022650696f);
    const ull PC3 = pack2(0.05550410866f, 0.05550410866f);
    const ull PC4 = pack2(0.00961812911f, 0.00961812911f);

    ull ax0 = 0, ay0 = 0, az0 = 0, aw0 = 0;
    ull ax1 = 0, ay1 = 0, az1 = 0, aw1 = 0;

    // warp covers 64 groups (= 256 t) of its t-quarter
    const ulonglong2* p = (const ulonglong2*)KV + (size_t)tq * 64 * 6;

    #pragma unroll 4
    for (int g = 0; g < 64; ++g, p += 6) {
        ulonglong2 kx = p[0], ky = p[1], kz = p[2];
        ull d00 = fma2(q0x, kx.x, fma2(q0y, ky.x, mul2(q0z, kz.x)));
        ull d01 = fma2(q0x, kx.y, fma2(q0y, ky.y, mul2(q0z, kz.y)));
        ull d10 = fma2(q1x, kx.x, fma2(q1y, ky.x, mul2(q1z, kz.x)));
        ull d11 = fma2(q1x, kx.y, fma2(q1y, ky.y, mul2(q1z, kz.y)));
        ull e00 = ex2p(d00);
        ull e01 = ex2p(d01);
        ull e10 = ex2p(d10);
        // e11 on FMA/ALU pipes: 2^d = 2^round(d) * 2^frac
        ull e11;
        {
            ull z = add2(d11, CR);                 // halves: RN(d)+C, int in mantissa
            ull t = add2(z, CNR);                  // round(d) exactly
            ull f = fma2(t, CN1, d11);             // frac in [-0.5, 0.5]
            ull gp = fma2(f, PC4, PC3);
            gp = fma2(f, gp, PC2);
            gp = fma2(f, gp, PC1);
            gp = mul2(f, gp);                      // 2^f - 1
            int nlo, nhi;
            asm("mov.b64 {%0, %1}, %2;" : "=r"(nlo), "=r"(nhi) : "l"(z));
            nlo = (nlo << 23) + 0x3F800000;        // (round(d)+127)<<23
            nhi = (nhi << 23) + 0x3F800000;
            ull s;
            asm("mov.b64 %0, {%1, %2};" : "=l"(s) : "r"(nlo), "r"(nhi));
            e11 = fma2(gp, s, s);                  // s * (1 + (2^f-1))
        }
        ulonglong2 vx = p[3], vy = p[4], vz = p[5];
        ax0 = fma2(e00, vx.x, ax0);  ay0 = fma2(e00, vy.x, ay0);
        az0 = fma2(e00, vz.x, az0);  aw0 = add2(aw0, e00);
        ax0 = fma2(e01, vx.y, ax0);  ay0 = fma2(e01, vy.y, ay0);
        az0 = fma2(e01, vz.y, az0);  aw0 = add2(aw0, e01);
        ax1 = fma2(e10, vx.x, ax1);  ay1 = fma2(e10, vy.x, ay1);
        az1 = fma2(e10, vz.x, az1);  aw1 = add2(aw1, e10);
        ax1 = fma2(e11, vx.y, ax1);  ay1 = fma2(e11, vy.y, ay1);
        az1 = fma2(e11, vz.y, az1);  aw1 = add2(aw1, e11);
    }

    // horizontal reduce packed halves -> per-row partial (num, den)
    float l, h;
    float n00, n01, n02, dd0, n10, n11, n12, dd1;
    unpack2(ax0, l, h); n00 = l + h;
    unpack2(ay0, l, h); n01 = l + h;
    unpack2(az0, l, h); n02 = l + h;
    unpack2(aw0, l, h); dd0 = l + h;
    unpack2(ax1, l, h); n10 = l + h;
    unpack2(ay1, l, h); n11 = l + h;
    unpack2(az1, l, h); n12 = l + h;
    unpack2(aw1, l, h); dd1 = l + h;

    // quarters 1..3 deposit partials; quarter 0 combines
    if (tq != 0) {
        cbuf[tq - 1][slot][0] = make_float4(n00, n01, n02, dd0);
        cbuf[tq - 1][slot][1] = make_float4(n10, n11, n12, dd1);
    }
    __syncthreads();

    float o00 = 0.f, o01 = 0.f, o02 = 0.f, o10 = 0.f, o11 = 0.f, o12 = 0.f;
    if (tq == 0) {
        #pragma unroll
        for (int qq = 0; qq < 3; ++qq) {
            float4 p0 = cbuf[qq][slot][0];
            float4 p1 = cbuf[qq][slot][1];
            n00 += p0.x; n01 += p0.y; n02 += p0.z; dd0 += p0.w;
            n10 += p1.x; n11 += p1.y; n12 += p1.z; dd1 += p1.w;
        }
        const float inv0 = 1.0f / dd0;
        const float inv1 = 1.0f / dd1;
        o00 = n00 * inv0; o01 = n01 * inv0; o02 = n02 * inv0;
        o10 = n10 * inv1; o11 = n11 * inv1; o12 = n12 * inv1;

        const size_t r0 = (size_t)b * SEQ + rc * 128 + slot;
        const size_t r1 = r0 + 64;
        float* c0 = g_att + (size_t)(attn * 3 + 0) * NROWS;
        float* c1 = g_att + (size_t)(attn * 3 + 1) * NROWS;
        float* c2 = g_att + (size_t)(attn * 3 + 2) * NROWS;
        c0[r0] = o00; c1[r0] = o01; c2[r0] = o02;
        c0[r1] = o10; c1[r1] = o11; c2[r1] = o12;
    }

    // ---- BN partial stats (non-quarter-0 warps contribute zeros) ----
    float sm[3], sq[3];
    sm[0] = o00 + o10; sm[1] = o01 + o11; sm[2] = o02 + o12;
    sq[0] = o00 * o00 + o10 * o10;
    sq[1] = o01 * o01 + o11 * o11;
    sq[2] = o02 * o02 + o12 * o12;
    #pragma unroll
    for (int off = 16; off > 0; off >>= 1) {
        #pragma unroll
        for (int i = 0; i < 3; ++i) {
            sm[i] += __shfl_down_sync(0xFFFFFFFFu, sm[i], off);
            sq[i] += __shfl_down_sync(0xFFFFFFFFu, sq[i], off);
        }
    }
    if (lane == 0) {
        #pragma unroll
        for (int i = 0; i < 3; ++i) {
            sred[warp * 6 + i]     = sm[i];
            sred[warp * 6 + 3 + i] = sq[i];
        }
    }
    __syncthreads();
    if (tid == 0) {
        float acc[6] = {0.f, 0.f, 0.f, 0.f, 0.f, 0.f};
        #pragma unroll
        for (int w = 0; w < 8; ++w)
            #pragma unroll
            for (int i = 0; i < 6; ++i)
                acc[i] += sred[w * 6 + i];
        #pragma unroll
        for (int i = 0; i < 6; ++i)
            g_part[blk * 6 + i] = acc[i];
    }
}

// ---------------------------------------------------------------------------
// Kernel C: finalize BN stats once (1 block; warp w = channel w)
// ---------------------------------------------------------------------------
__global__ __launch_bounds__(288) void stats_kernel(
    const float* __restrict__ gamma, const float* __restrict__ beta)
{
    const int w = threadIdx.x >> 5, lane = threadIdx.x & 31;
    if (w >= 9) return;
    const int at = w / 3, d = w - at * 3;
    float sm = 0.f, sq = 0.f;
    for (int i = lane; i < NB * 8; i += 32) {      // 384 blocks per attn
        const float* p = g_part + (size_t)(at * NB * 8 + i) * 6;
        sm += p[d];
        sq += p[3 + d];
    }
    #pragma unroll
    for (int off = 16; off > 0; off >>= 1) {
        sm += __shfl_down_sync(0xFFFFFFFFu, sm, off);
        sq += __shfl_down_sync(0xFFFFFFFFu, sq, off);
    }
    if (lane == 0) {
        const float mean = sm * (1.0f / NROWS);
        const float var  = sq * (1.0f / NROWS) - mean * mean;
        const float inv  = rsqrtf(var + 1e-5f);
        const float sc   = gamma[w] * inv;
        g_ss[w]     = sc;
        g_ss[9 + w] = beta[w] - mean * sc;
    }
}

// ---------------------------------------------------------------------------
// Kernel B: BN + FC. 4 consecutive rows/thread -> float4 LDG + float4 STG.
// ---------------------------------------------------------------------------
__global__ __launch_bounds__(256) void bnfc_kernel(
    const float* __restrict__ fcw, const float* __restrict__ fcb,
    float* __restrict__ out)
{
    __shared__ float ss[18];
    __shared__ float w[27];
    const int tid = threadIdx.x;
    if (tid < 18) ss[tid] = g_ss[tid];
    if (tid < 27) w[tid] = fcw[tid];
    __syncthreads();

    const int r0 = (blockIdx.x * 256 + tid) * 4;
    float n[4][9];
    #pragma unroll
    for (int c = 0; c < 9; ++c) {
        float4 v = *(const float4*)(g_att + (size_t)c * NROWS + r0);
        n[0][c] = fmaf(v.x, ss[c], ss[9 + c]);
        n[1][c] = fmaf(v.y, ss[c], ss[9 + c]);
        n[2][c] = fmaf(v.z, ss[c], ss[9 + c]);
        n[3][c] = fmaf(v.w, ss[c], ss[9 + c]);
    }
    float y[4][3];
    #pragma unroll
    for (int r = 0; r < 4; ++r)
        #pragma unroll
        for (int j = 0; j < 3; ++j) {
            float acc = fcb[j];
            #pragma unroll
            for (int c = 0; c < 9; ++c)
                acc = fmaf(n[r][c], w[j * 9 + c], acc);
            y[r][j] = acc;
        }
    float4* o = (float4*)(out + (size_t)r0 * 3);
    o[0] = make_float4(y[0][0], y[0][1], y[0][2], y[1][0]);
    o[1] = make_float4(y[1][1], y[1][2], y[2][0], y[2][1]);
    o[2] = make_float4(y[2][2], y[3][0], y[3][1], y[3][2]);
}

// ---------------------------------------------------------------------------
extern "C" void kernel_launch(void* const* d_in, const int* in_sizes, int n_in,
                              void* d_out, int out_size)
{
    const float* x     = (const float*)d_in[0];
    const float* WQ    = (const float*)d_in[1];
    const float* bQ    = (const float*)d_in[2];
    const float* WK    = (const float*)d_in[3];
    const float* bK    = (const float*)d_in[4];
    const float* WV    = (const float*)d_in[5];
    const float* bV    = (const float*)d_in[6];
    const float* gamma = (const float*)d_in[7];
    const float* beta  = (const float*)d_in[8];
    const float* fcw   = (const float*)d_in[9];
    const float* fcb   = (const float*)d_in[10];

    attn_kernel<<<NBLK_A, TPB_A>>>(x, WQ, bQ, WK, bK, WV, bV);
    stats_kernel<<<1, 288>>>(gamma, beta);
    bnfc_kernel<<<NROWS / 1024, 256>>>(fcw, fcb, (float*)d_out);
}

// round 11
// speedup vs baseline: 1.1113x; 1.1113x over previous
#include <cuda_runtime.h>

#define SEQ 1024
#define NB  48
#define NROWS (NB * SEQ)           // 49152 rows, 9 channels
#define NBLK_A 144                  // 3 attns * 48 batches
#define TPB_A 512

typedef unsigned long long ull;

// scratch (allocation-free rule: __device__ globals)
__device__ float g_att[9 * NROWS];      // SoA: [channel][row]
__device__ float g_part[NBLK_A * 6];    // per-block partial sum/sumsq (3 ch each)
__device__ float g_ss[18];              // BN scale[9], shift[9]
__device__ int   g_ctr = 0;             // last-block counter (self-resetting)

// ---------------- packed f32x2 helpers (Blackwell) ----------------
__device__ __forceinline__ ull pack2(float lo, float hi) {
    ull r; asm("mov.b64 %0, {%1, %2};" : "=l"(r) : "f"(lo), "f"(hi)); return r;
}
__device__ __forceinline__ void unpack2(ull v, float& lo, float& hi) {
    asm("mov.b64 {%0, %1}, %2;" : "=f"(lo), "=f"(hi) : "l"(v));
}
__device__ __forceinline__ ull fma2(ull a, ull b, ull c) {
    ull d; asm("fma.rn.f32x2 %0, %1, %2, %3;" : "=l"(d) : "l"(a), "l"(b), "l"(c)); return d;
}
__device__ __forceinline__ ull mul2(ull a, ull b) {
    ull d; asm("mul.rn.f32x2 %0, %1, %2;" : "=l"(d) : "l"(a), "l"(b)); return d;
}
__device__ __forceinline__ ull add2(ull a, ull b) {
    ull d; asm("add.rn.f32x2 %0, %1, %2;" : "=l"(d) : "l"(a), "l"(b)); return d;
}
__device__ __forceinline__ ull ex2_2(ull d) {
    ull e;
    asm("{\n\t"
        ".reg .f32 dl, dh, el, eh;\n\t"
        "mov.b64 {dl, dh}, %1;\n\t"
        "ex2.approx.f32 el, dl;\n\t"
        "ex2.approx.f32 eh, dh;\n\t"
        "mov.b64 %0, {el, eh};\n\t"
        "}" : "=l"(e) : "l"(d));
    return e;
}

// ---------------------------------------------------------------------------
// Kernel A: fused projection + cross attention + BN partials + (last block)
// BN stats finalize. block = (attn_idx, batch). K,V component-major in smem;
// each thread owns 2 rows x 1024 t. EXACT r2 hot loop (best measured).
// ---------------------------------------------------------------------------
__global__ __launch_bounds__(TPB_A) void attn_kernel(
    const float* __restrict__ x,
    const float* __restrict__ WQ, const float* __restrict__ bQ,
    const float* __restrict__ WK, const float* __restrict__ bK,
    const float* __restrict__ WV, const float* __restrict__ bV,
    const float* __restrict__ gamma, const float* __restrict__ beta)
{
    __shared__ __align__(16) float Kx[SEQ], Ky[SEQ], Kz[SEQ];
    __shared__ __align__(16) float Vx[SEQ], Vy[SEQ], Vz[SEQ];
    __shared__ float sred[16 * 6];
    __shared__ int amlast;

    const int blk  = blockIdx.x;
    const int attn = blk / NB;
    const int b    = blk - attn * NB;

    // a1=attn(Q2,K0,V1), a2=attn(Q0,K1,V2), a3=attn(Q1,K2,V0)
    const int qmap[3] = {2, 0, 1};
    const int vmap[3] = {1, 2, 0};
    const int qb = qmap[attn], kb = attn, vb = vmap[attn];

    const int tid = threadIdx.x;

    // ---- phase 1: K,V tiles (3x3 projection on the fly) ----
    {
        const float* wk = WK + kb * 9;  const float* bk = bK + kb * 3;
        const float* wv = WV + vb * 9;  const float* bv = bV + vb * 3;
        #pragma unroll
        for (int it = 0; it < SEQ / TPB_A; ++it) {
            int t = tid + it * TPB_A;
            const float* xk = x + ((size_t)(kb * NB + b) * SEQ + t) * 3;
            float x0 = xk[0], x1 = xk[1], x2 = xk[2];
            Kx[t] = fmaf(wk[0], x0, fmaf(wk[1], x1, fmaf(wk[2], x2, bk[0])));
            Ky[t] = fmaf(wk[3], x0, fmaf(wk[4], x1, fmaf(wk[5], x2, bk[1])));
            Kz[t] = fmaf(wk[6], x0, fmaf(wk[7], x1, fmaf(wk[8], x2, bk[2])));

            const float* xv = x + ((size_t)(vb * NB + b) * SEQ + t) * 3;
            float y0 = xv[0], y1 = xv[1], y2 = xv[2];
            Vx[t] = fmaf(wv[0], y0, fmaf(wv[1], y1, fmaf(wv[2], y2, bv[0])));
            Vy[t] = fmaf(wv[3], y0, fmaf(wv[4], y1, fmaf(wv[5], y2, bv[1])));
            Vz[t] = fmaf(wv[6], y0, fmaf(wv[7], y1, fmaf(wv[8], y2, bv[2])));
        }
    }
    __syncthreads();

    // ---- per-thread Q for rows s0=tid, s1=tid+512; fold log2e/sqrt(3) ----
    const float qscale = 1.4426950408889634f / 1.7320508075688772f;
    ull q0x, q0y, q0z, q1x, q1y, q1z;
    {
        const float* wq = WQ + qb * 9;  const float* bq = bQ + qb * 3;
        const float* xq = x + ((size_t)(qb * NB + b) * SEQ + tid) * 3;
        float x0 = xq[0], x1 = xq[1], x2 = xq[2];
        float a = fmaf(wq[0], x0, fmaf(wq[1], x1, fmaf(wq[2], x2, bq[0]))) * qscale;
        float c = fmaf(wq[3], x0, fmaf(wq[4], x1, fmaf(wq[5], x2, bq[1]))) * qscale;
        float d = fmaf(wq[6], x0, fmaf(wq[7], x1, fmaf(wq[8], x2, bq[2]))) * qscale;
        q0x = pack2(a, a); q0y = pack2(c, c); q0z = pack2(d, d);
        xq = x + ((size_t)(qb * NB + b) * SEQ + tid + TPB_A) * 3;
        x0 = xq[0]; x1 = xq[1]; x2 = xq[2];
        a = fmaf(wq[0], x0, fmaf(wq[1], x1, fmaf(wq[2], x2, bq[0]))) * qscale;
        c = fmaf(wq[3], x0, fmaf(wq[4], x1, fmaf(wq[5], x2, bq[1]))) * qscale;
        d = fmaf(wq[6], x0, fmaf(wq[7], x1, fmaf(wq[8], x2, bq[2]))) * qscale;
        q1x = pack2(a, a); q1y = pack2(c, c); q1z = pack2(d, d);
    }

    const ull* pKx = (const ull*)Kx; const ull* pKy = (const ull*)Ky;
    const ull* pKz = (const ull*)Kz; const ull* pVx = (const ull*)Vx;
    const ull* pVy = (const ull*)Vy; const ull* pVz = (const ull*)Vz;

    ull ax0 = 0, ay0 = 0, az0 = 0, aw0 = 0;
    ull ax1 = 0, ay1 = 0, az1 = 0, aw1 = 0;

    #pragma unroll 4
    for (int t2 = 0; t2 < SEQ / 2; ++t2) {
        ull kx = pKx[t2], ky = pKy[t2], kz = pKz[t2];
        ull vx = pVx[t2], vy = pVy[t2], vz = pVz[t2];

        ull d0 = fma2(q0x, kx, fma2(q0y, ky, mul2(q0z, kz)));
        ull e0 = ex2_2(d0);
        ax0 = fma2(e0, vx, ax0);
        ay0 = fma2(e0, vy, ay0);
        az0 = fma2(e0, vz, az0);
        aw0 = add2(aw0, e0);

        ull d1 = fma2(q1x, kx, fma2(q1y, ky, mul2(q1z, kz)));
        ull e1 = ex2_2(d1);
        ax1 = fma2(e1, vx, ax1);
        ay1 = fma2(e1, vy, ay1);
        az1 = fma2(e1, vz, az1);
        aw1 = add2(aw1, e1);
    }

    // horizontal reduce packed halves
    float l, h;
    unpack2(aw0, l, h); const float inv0 = 1.0f / (l + h);
    unpack2(aw1, l, h); const float inv1 = 1.0f / (l + h);
    unpack2(ax0, l, h); const float o00 = (l + h) * inv0;
    unpack2(ay0, l, h); const float o01 = (l + h) * inv0;
    unpack2(az0, l, h); const float o02 = (l + h) * inv0;
    unpack2(ax1, l, h); const float o10 = (l + h) * inv1;
    unpack2(ay1, l, h); const float o11 = (l + h) * inv1;
    unpack2(az1, l, h); const float o12 = (l + h) * inv1;

    // SoA coalesced store: channel = attn*3 + i
    {
        const size_t r0 = (size_t)b * SEQ + tid;
        const size_t r1 = r0 + TPB_A;
        float* c0 = g_att + (size_t)(attn * 3 + 0) * NROWS;
        float* c1 = g_att + (size_t)(attn * 3 + 1) * NROWS;
        float* c2 = g_att + (size_t)(attn * 3 + 2) * NROWS;
        c0[r0] = o00; c1[r0] = o01; c2[r0] = o02;
        c0[r1] = o10; c1[r1] = o11; c2[r1] = o12;
    }

    // ---- BN partial stats (deterministic block reduction) ----
    float sm[3], sq[3];
    sm[0] = o00 + o10; sm[1] = o01 + o11; sm[2] = o02 + o12;
    sq[0] = o00 * o00 + o10 * o10;
    sq[1] = o01 * o01 + o11 * o11;
    sq[2] = o02 * o02 + o12 * o12;

    #pragma unroll
    for (int off = 16; off > 0; off >>= 1) {
        #pragma unroll
        for (int i = 0; i < 3; ++i) {
            sm[i] += __shfl_down_sync(0xFFFFFFFFu, sm[i], off);
            sq[i] += __shfl_down_sync(0xFFFFFFFFu, sq[i], off);
        }
    }
    const int warp = tid >> 5, lane = tid & 31;
    if (lane == 0) {
        #pragma unroll
        for (int i = 0; i < 3; ++i) {
            sred[warp * 6 + i]     = sm[i];
            sred[warp * 6 + 3 + i] = sq[i];
        }
    }
    __syncthreads();
    if (tid == 0) {
        float acc[6] = {0.f, 0.f, 0.f, 0.f, 0.f, 0.f};
        #pragma unroll
        for (int w = 0; w < 16; ++w)
            #pragma unroll
            for (int i = 0; i < 6; ++i)
                acc[i] += sred[w * 6 + i];
        #pragma unroll
        for (int i = 0; i < 6; ++i)
            g_part[blk * 6 + i] = acc[i];
        // publish partials, then count arrivals (threadFenceReduction pattern)
        __threadfence();
        int old = atomicAdd(&g_ctr, 1);
        amlast = (old == NBLK_A - 1);
    }
    __syncthreads();

    // ---- last block finalizes BN stats (deterministic fixed-order sums) ----
    if (amlast) {
        const int w = warp;
        if (w < 9) {
            const int at = w / 3, d = w - at * 3;
            float fsm = 0.f, fsq = 0.f;
            for (int i = lane; i < NB; i += 32) {
                const float* p = g_part + (size_t)(at * NB + i) * 6;
                fsm += p[d];
                fsq += p[3 + d];
            }
            #pragma unroll
            for (int off = 16; off > 0; off >>= 1) {
                fsm += __shfl_down_sync(0xFFFFFFFFu, fsm, off);
                fsq += __shfl_down_sync(0xFFFFFFFFu, fsq, off);
            }
            if (lane == 0) {
                const float mean = fsm * (1.0f / NROWS);
                const float var  = fsq * (1.0f / NROWS) - mean * mean;
                const float inv  = rsqrtf(var + 1e-5f);
                const float sc   = gamma[w] * inv;
                g_ss[w]     = sc;
                g_ss[9 + w] = beta[w] - mean * sc;
            }
        }
        if (tid == 0) g_ctr = 0;   // self-reset for next graph replay
    }
}

// ---------------------------------------------------------------------------
// Kernel B: BN + FC. 4 consecutive rows/thread -> float4 LDG + float4 STG.
// ---------------------------------------------------------------------------
__global__ __launch_bounds__(256) void bnfc_kernel(
    const float* __restrict__ fcw, const float* __restrict__ fcb,
    float* __restrict__ out)
{
    __shared__ float ss[18];
    __shared__ float w[27];
    const int tid = threadIdx.x;
    if (tid < 18) ss[tid] = g_ss[tid];
    if (tid < 27) w[tid] = fcw[tid];
    __syncthreads();

    const int r0 = (blockIdx.x * 256 + tid) * 4;   // grid covers NROWS exactly
    float n[4][9];
    #pragma unroll
    for (int c = 0; c < 9; ++c) {
        float4 v = *(const float4*)(g_att + (size_t)c * NROWS + r0);
        n[0][c] = fmaf(v.x, ss[c], ss[9 + c]);
        n[1][c] = fmaf(v.y, ss[c], ss[9 + c]);
        n[2][c] = fmaf(v.z, ss[c], ss[9 + c]);
        n[3][c] = fmaf(v.w, ss[c], ss[9 + c]);
    }
    float y[4][3];
    #pragma unroll
    for (int r = 0; r < 4; ++r)
        #pragma unroll
        for (int j = 0; j < 3; ++j) {
            float acc = fcb[j];
            #pragma unroll
            for (int c = 0; c < 9; ++c)
                acc = fmaf(n[r][c], w[j * 9 + c], acc);
            y[r][j] = acc;
        }
    float4* o = (float4*)(out + (size_t)r0 * 3);
    o[0] = make_float4(y[0][0], y[0][1], y[0][2], y[1][0]);
    o[1] = make_float4(y[1][1], y[1][2], y[2][0], y[2][1]);
    o[2] = make_float4(y[2][2], y[3][0], y[3][1], y[3][2]);
}

// ---------------------------------------------------------------------------
extern "C" void kernel_launch(void* const* d_in, const int* in_sizes, int n_in,
                              void* d_out, int out_size)
{
    const float* x     = (const float*)d_in[0];
    const float* WQ    = (const float*)d_in[1];
    const float* bQ    = (const float*)d_in[2];
    const float* WK    = (const float*)d_in[3];
    const float* bK    = (const float*)d_in[4];
    const float* WV    = (const float*)d_in[5];
    const float* bV    = (const float*)d_in[6];
    const float* gamma = (const float*)d_in[7];
    const float* beta  = (const float*)d_in[8];
    const float* fcw   = (const float*)d_in[9];
    const float* fcb   = (const float*)d_in[10];

    attn_kernel<<<NBLK_A, TPB_A>>>(x, WQ, bQ, WK, bK, WV, bV, gamma, beta);
    bnfc_kernel<<<NROWS / 1024, 256>>>(fcw, fcb, (float*)d_out);
}

// round 14
// speedup vs baseline: 1.1324x; 1.0190x over previous
#include <cuda_runtime.h>

#define SEQ 1024
#define NB  48
#define NROWS (NB * SEQ)           // 49152 rows, 9 channels
#define NBLK_A 144                  // 3 attns * 48 batches
#define TPB_A 512

typedef unsigned long long ull;

// scratch (allocation-free rule: __device__ globals)
__device__ float g_att[9 * NROWS];      // SoA: [channel][row]
__device__ float g_part[NBLK_A * 6];    // per-block partial sum/sumsq (3 ch each)
__device__ float g_ss[18];              // BN scale[9], shift[9]
__device__ int   g_ctr = 0;             // last-block counter (self-resetting)

// ---------------- packed f32x2 helpers (Blackwell) ----------------
__device__ __forceinline__ ull pack2(float lo, float hi) {
    ull r; asm("mov.b64 %0, {%1, %2};" : "=l"(r) : "f"(lo), "f"(hi)); return r;
}
__device__ __forceinline__ void unpack2(ull v, float& lo, float& hi) {
    asm("mov.b64 {%0, %1}, %2;" : "=f"(lo), "=f"(hi) : "l"(v));
}
__device__ __forceinline__ ull fma2(ull a, ull b, ull c) {
    ull d; asm("fma.rn.f32x2 %0, %1, %2, %3;" : "=l"(d) : "l"(a), "l"(b), "l"(c)); return d;
}
__device__ __forceinline__ ull mul2(ull a, ull b) {
    ull d; asm("mul.rn.f32x2 %0, %1, %2;" : "=l"(d) : "l"(a), "l"(b)); return d;
}
__device__ __forceinline__ ull add2(ull a, ull b) {
    ull d; asm("add.rn.f32x2 %0, %1, %2;" : "=l"(d) : "l"(a), "l"(b)); return d;
}
__device__ __forceinline__ ull ex2_2(ull d) {
    ull e;
    asm("{\n\t"
        ".reg .f32 dl, dh, el, eh;\n\t"
        "mov.b64 {dl, dh}, %1;\n\t"
        "ex2.approx.f32 el, dl;\n\t"
        "ex2.approx.f32 eh, dh;\n\t"
        "mov.b64 %0, {el, eh};\n\t"
        "}" : "=l"(e) : "l"(d));
    return e;
}

// ---------------------------------------------------------------------------
// Kernel A: fused projection + cross attention + BN partials + (last block)
// BN stats finalize. block = (attn_idx, batch). K,V component-major in smem;
// each thread owns 2 rows x 1024 t. UNCHANGED from r11 (best measured).
// ---------------------------------------------------------------------------
__global__ __launch_bounds__(TPB_A) void attn_kernel(
    const float* __restrict__ x,
    const float* __restrict__ WQ, const float* __restrict__ bQ,
    const float* __restrict__ WK, const float* __restrict__ bK,
    const float* __restrict__ WV, const float* __restrict__ bV,
    const float* __restrict__ gamma, const float* __restrict__ beta)
{
    __shared__ __align__(16) float Kx[SEQ], Ky[SEQ], Kz[SEQ];
    __shared__ __align__(16) float Vx[SEQ], Vy[SEQ], Vz[SEQ];
    __shared__ float sred[16 * 6];
    __shared__ int amlast;

    const int blk  = blockIdx.x;
    const int attn = blk / NB;
    const int b    = blk - attn * NB;

    // a1=attn(Q2,K0,V1), a2=attn(Q0,K1,V2), a3=attn(Q1,K2,V0)
    const int qmap[3] = {2, 0, 1};
    const int vmap[3] = {1, 2, 0};
    const int qb = qmap[attn], kb = attn, vb = vmap[attn];

    const int tid = threadIdx.x;

    // ---- phase 1: K,V tiles (3x3 projection on the fly) ----
    {
        const float* wk = WK + kb * 9;  const float* bk = bK + kb * 3;
        const float* wv = WV + vb * 9;  const float* bv = bV + vb * 3;
        #pragma unroll
        for (int it = 0; it < SEQ / TPB_A; ++it) {
            int t = tid + it * TPB_A;
            const float* xk = x + ((size_t)(kb * NB + b) * SEQ + t) * 3;
            float x0 = xk[0], x1 = xk[1], x2 = xk[2];
            Kx[t] = fmaf(wk[0], x0, fmaf(wk[1], x1, fmaf(wk[2], x2, bk[0])));
            Ky[t] = fmaf(wk[3], x0, fmaf(wk[4], x1, fmaf(wk[5], x2, bk[1])));
            Kz[t] = fmaf(wk[6], x0, fmaf(wk[7], x1, fmaf(wk[8], x2, bk[2])));

            const float* xv = x + ((size_t)(vb * NB + b) * SEQ + t) * 3;
            float y0 = xv[0], y1 = xv[1], y2 = xv[2];
            Vx[t] = fmaf(wv[0], y0, fmaf(wv[1], y1, fmaf(wv[2], y2, bv[0])));
            Vy[t] = fmaf(wv[3], y0, fmaf(wv[4], y1, fmaf(wv[5], y2, bv[1])));
            Vz[t] = fmaf(wv[6], y0, fmaf(wv[7], y1, fmaf(wv[8], y2, bv[2])));
        }
    }
    __syncthreads();

    // ---- per-thread Q for rows s0=tid, s1=tid+512; fold log2e/sqrt(3) ----
    const float qscale = 1.4426950408889634f / 1.7320508075688772f;
    ull q0x, q0y, q0z, q1x, q1y, q1z;
    {
        const float* wq = WQ + qb * 9;  const float* bq = bQ + qb * 3;
        const float* xq = x + ((size_t)(qb * NB + b) * SEQ + tid) * 3;
        float x0 = xq[0], x1 = xq[1], x2 = xq[2];
        float a = fmaf(wq[0], x0, fmaf(wq[1], x1, fmaf(wq[2], x2, bq[0]))) * qscale;
        float c = fmaf(wq[3], x0, fmaf(wq[4], x1, fmaf(wq[5], x2, bq[1]))) * qscale;
        float d = fmaf(wq[6], x0, fmaf(wq[7], x1, fmaf(wq[8], x2, bq[2]))) * qscale;
        q0x = pack2(a, a); q0y = pack2(c, c); q0z = pack2(d, d);
        xq = x + ((size_t)(qb * NB + b) * SEQ + tid + TPB_A) * 3;
        x0 = xq[0]; x1 = xq[1]; x2 = xq[2];
        a = fmaf(wq[0], x0, fmaf(wq[1], x1, fmaf(wq[2], x2, bq[0]))) * qscale;
        c = fmaf(wq[3], x0, fmaf(wq[4], x1, fmaf(wq[5], x2, bq[1]))) * qscale;
        d = fmaf(wq[6], x0, fmaf(wq[7], x1, fmaf(wq[8], x2, bq[2]))) * qscale;
        q1x = pack2(a, a); q1y = pack2(c, c); q1z = pack2(d, d);
    }

    const ull* pKx = (const ull*)Kx; const ull* pKy = (const ull*)Ky;
    const ull* pKz = (const ull*)Kz; const ull* pVx = (const ull*)Vx;
    const ull* pVy = (const ull*)Vy; const ull* pVz = (const ull*)Vz;

    ull ax0 = 0, ay0 = 0, az0 = 0, aw0 = 0;
    ull ax1 = 0, ay1 = 0, az1 = 0, aw1 = 0;

    #pragma unroll 4
    for (int t2 = 0; t2 < SEQ / 2; ++t2) {
        ull kx = pKx[t2], ky = pKy[t2], kz = pKz[t2];
        ull vx = pVx[t2], vy = pVy[t2], vz = pVz[t2];

        ull d0 = fma2(q0x, kx, fma2(q0y, ky, mul2(q0z, kz)));
        ull e0 = ex2_2(d0);
        ax0 = fma2(e0, vx, ax0);
        ay0 = fma2(e0, vy, ay0);
        az0 = fma2(e0, vz, az0);
        aw0 = add2(aw0, e0);

        ull d1 = fma2(q1x, kx, fma2(q1y, ky, mul2(q1z, kz)));
        ull e1 = ex2_2(d1);
        ax1 = fma2(e1, vx, ax1);
        ay1 = fma2(e1, vy, ay1);
        az1 = fma2(e1, vz, az1);
        aw1 = add2(aw1, e1);
    }

    // horizontal reduce packed halves
    float l, h;
    unpack2(aw0, l, h); const float inv0 = 1.0f / (l + h);
    unpack2(aw1, l, h); const float inv1 = 1.0f / (l + h);
    unpack2(ax0, l, h); const float o00 = (l + h) * inv0;
    unpack2(ay0, l, h); const float o01 = (l + h) * inv0;
    unpack2(az0, l, h); const float o02 = (l + h) * inv0;
    unpack2(ax1, l, h); const float o10 = (l + h) * inv1;
    unpack2(ay1, l, h); const float o11 = (l + h) * inv1;
    unpack2(az1, l, h); const float o12 = (l + h) * inv1;

    // SoA coalesced store: channel = attn*3 + i
    {
        const size_t r0 = (size_t)b * SEQ + tid;
        const size_t r1 = r0 + TPB_A;
        float* c0 = g_att + (size_t)(attn * 3 + 0) * NROWS;
        float* c1 = g_att + (size_t)(attn * 3 + 1) * NROWS;
        float* c2 = g_att + (size_t)(attn * 3 + 2) * NROWS;
        c0[r0] = o00; c1[r0] = o01; c2[r0] = o02;
        c0[r1] = o10; c1[r1] = o11; c2[r1] = o12;
    }

    // ---- BN partial stats (deterministic block reduction) ----
    float sm[3], sq[3];
    sm[0] = o00 + o10; sm[1] = o01 + o11; sm[2] = o02 + o12;
    sq[0] = o00 * o00 + o10 * o10;
    sq[1] = o01 * o01 + o11 * o11;
    sq[2] = o02 * o02 + o12 * o12;

    #pragma unroll
    for (int off = 16; off > 0; off >>= 1) {
        #pragma unroll
        for (int i = 0; i < 3; ++i) {
            sm[i] += __shfl_down_sync(0xFFFFFFFFu, sm[i], off);
            sq[i] += __shfl_down_sync(0xFFFFFFFFu, sq[i], off);
        }
    }
    const int warp = tid >> 5, lane = tid & 31;
    if (lane == 0) {
        #pragma unroll
        for (int i = 0; i < 3; ++i) {
            sred[warp * 6 + i]     = sm[i];
            sred[warp * 6 + 3 + i] = sq[i];
        }
    }
    __syncthreads();
    if (tid == 0) {
        float acc[6] = {0.f, 0.f, 0.f, 0.f, 0.f, 0.f};
        #pragma unroll
        for (int w = 0; w < 16; ++w)
            #pragma unroll
            for (int i = 0; i < 6; ++i)
                acc[i] += sred[w * 6 + i];
        #pragma unroll
        for (int i = 0; i < 6; ++i)
            g_part[blk * 6 + i] = acc[i];
        // publish partials, then count arrivals (threadFenceReduction pattern)
        __threadfence();
        int old = atomicAdd(&g_ctr, 1);
        amlast = (old == NBLK_A - 1);
    }
    __syncthreads();

    // ---- last block finalizes BN stats (deterministic fixed-order sums) ----
    if (amlast) {
        const int w = warp;
        if (w < 9) {
            const int at = w / 3, d = w - at * 3;
            float fsm = 0.f, fsq = 0.f;
            for (int i = lane; i < NB; i += 32) {
                const float* p = g_part + (size_t)(at * NB + i) * 6;
                fsm += p[d];
                fsq += p[3 + d];
            }
            #pragma unroll
            for (int off = 16; off > 0; off >>= 1) {
                fsm += __shfl_down_sync(0xFFFFFFFFu, fsm, off);
                fsq += __shfl_down_sync(0xFFFFFFFFu, fsq, off);
            }
            if (lane == 0) {
                const float mean = fsm * (1.0f / NROWS);
                const float var  = fsq * (1.0f / NROWS) - mean * mean;
                const float inv  = rsqrtf(var + 1e-5f);
                const float sc   = gamma[w] * inv;
                g_ss[w]     = sc;
                g_ss[9 + w] = beta[w] - mean * sc;
            }
        }
        if (tid == 0) g_ctr = 0;   // self-reset for next graph replay
    }
}

// ---------------------------------------------------------------------------
// Kernel B: BN + FC. ONE ROW PER THREAD (49152 threads, 96 blocks x 512).
// 9 independent coalesced scalar LDGs issued up-front (MLP ~ 9); epilogue
// latency covered by sheer thread count instead of per-thread chains.
// ---------------------------------------------------------------------------
__global__ __launch_bounds__(512) void bnfc_kernel(
    const float* __restrict__ fcw, const float* __restrict__ fcb,
    float* __restrict__ out)
{
    __shared__ float ss[18];
    __shared__ float w[27];
    __shared__ float fb[3];
    const int tid = threadIdx.x;
    if (tid < 18) ss[tid] = g_ss[tid];
    if (tid < 27) w[tid] = fcw[tid];
    if (tid < 3)  fb[tid] = fcb[tid];
    __syncthreads();

    const int row = blockIdx.x * 512 + tid;   // grid covers NROWS exactly

    // batch all 9 loads first (independent; compiler front-batches -> MLP 9)
    float a[9];
    #pragma unroll
    for (int c = 0; c < 9; ++c)
        a[c] = g_att[(size_t)c * NROWS + row];

    float n[9];
    #pragma unroll
    for (int c = 0; c < 9; ++c)
        n[c] = fmaf(a[c], ss[c], ss[9 + c]);

    float y0 = fb[0], y1 = fb[1], y2 = fb[2];
    #pragma unroll
    for (int c = 0; c < 9; ++c) {
        y0 = fmaf(n[c], w[c], y0);
        y1 = fmaf(n[c], w[9 + c], y1);
        y2 = fmaf(n[c], w[18 + c], y2);
    }
    float* o = out + (size_t)row * 3;
    o[0] = y0; o[1] = y1; o[2] = y2;
}

// ---------------------------------------------------------------------------
extern "C" void kernel_launch(void* const* d_in, const int* in_sizes, int n_in,
                              void* d_out, int out_size)
{
    const float* x     = (const float*)d_in[0];
    const float* WQ    = (const float*)d_in[1];
    const float* bQ    = (const float*)d_in[2];
    const float* WK    = (const float*)d_in[3];
    const float* bK    = (const float*)d_in[4];
    const float* WV    = (const float*)d_in[5];
    const float* bV    = (const float*)d_in[6];
    const float* gamma = (const float*)d_in[7];
    const float* beta  = (const float*)d_in[8];
    const float* fcw   = (const float*)d_in[9];
    const float* fcb   = (const float*)d_in[10];

    attn_kernel<<<NBLK_A, TPB_A>>>(x, WQ, bQ, WK, bK, WV, bV, gamma, beta);
    bnfc_kernel<<<NROWS / 512, 512>>>(fcw, fcb, (float*)d_out);
}

// round 15
// speedup vs baseline: 1.1438x; 1.0101x over previous
#include <cuda_runtime.h>

#define SEQ 1024
#define NB  48
#define NROWS (NB * SEQ)           // 49152 rows, 9 channels
#define NBLK_A 144                  // 3 attns * 48 batches (single wave!)
#define TPB_A 512

typedef unsigned long long ull;

// scratch (allocation-free rule: __device__ globals)
__device__ float g_att[9 * NROWS];      // SoA: [channel][row]
__device__ float g_part[NBLK_A * 6];    // per-block partial sum/sumsq (3 ch each)
__device__ float g_ss[18];              // BN scale[9], shift[9]
__device__ int   g_ctr = 0;             // arrival counter (self-resetting)
__device__ int   g_rel = 0;             // release epoch (monotonic)

// ---------------- packed f32x2 helpers (Blackwell) ----------------
__device__ __forceinline__ ull pack2(float lo, float hi) {
    ull r; asm("mov.b64 %0, {%1, %2};" : "=l"(r) : "f"(lo), "f"(hi)); return r;
}
__device__ __forceinline__ void unpack2(ull v, float& lo, float& hi) {
    asm("mov.b64 {%0, %1}, %2;" : "=f"(lo), "=f"(hi) : "l"(v));
}
__device__ __forceinline__ ull fma2(ull a, ull b, ull c) {
    ull d; asm("fma.rn.f32x2 %0, %1, %2, %3;" : "=l"(d) : "l"(a), "l"(b), "l"(c)); return d;
}
__device__ __forceinline__ ull mul2(ull a, ull b) {
    ull d; asm("mul.rn.f32x2 %0, %1, %2;" : "=l"(d) : "l"(a), "l"(b)); return d;
}
__device__ __forceinline__ ull add2(ull a, ull b) {
    ull d; asm("add.rn.f32x2 %0, %1, %2;" : "=l"(d) : "l"(a), "l"(b)); return d;
}
__device__ __forceinline__ ull ex2_2(ull d) {
    ull e;
    asm("{\n\t"
        ".reg .f32 dl, dh, el, eh;\n\t"
        "mov.b64 {dl, dh}, %1;\n\t"
        "ex2.approx.f32 el, dl;\n\t"
        "ex2.approx.f32 eh, dh;\n\t"
        "mov.b64 %0, {el, eh};\n\t"
        "}" : "=l"(e) : "l"(d));
    return e;
}

// ---------------------------------------------------------------------------
// SINGLE persistent-wave kernel: projection + cross attention + BN stats
// (threadFenceReduction) + software global barrier + fused BN+FC epilogue.
// 144 blocks <= 148 SMs -> all co-resident -> spin barrier is deadlock-free.
// ---------------------------------------------------------------------------
__global__ __launch_bounds__(TPB_A) void attn_kernel(
    const float* __restrict__ x,
    const float* __restrict__ WQ, const float* __restrict__ bQ,
    const float* __restrict__ WK, const float* __restrict__ bK,
    const float* __restrict__ WV, const float* __restrict__ bV,
    const float* __restrict__ gamma, const float* __restrict__ beta,
    const float* __restrict__ fcw, const float* __restrict__ fcb,
    float* __restrict__ out)
{
    __shared__ __align__(16) float Kx[SEQ], Ky[SEQ], Kz[SEQ];
    __shared__ __align__(16) float Vx[SEQ], Vy[SEQ], Vz[SEQ];
    __shared__ float sred[16 * 6];
    __shared__ int s_rel0;
    __shared__ int amlast;

    const int blk  = blockIdx.x;
    const int attn = blk / NB;
    const int b    = blk - attn * NB;
    const int tid  = threadIdx.x;

    // snapshot release epoch BEFORE contributing (snapshot < release, always)
    if (tid == 0) s_rel0 = atomicAdd(&g_rel, 0);

    // a1=attn(Q2,K0,V1), a2=attn(Q0,K1,V2), a3=attn(Q1,K2,V0)
    const int qmap[3] = {2, 0, 1};
    const int vmap[3] = {1, 2, 0};
    const int qb = qmap[attn], kb = attn, vb = vmap[attn];

    // ---- phase 1: K,V tiles (3x3 projection on the fly) ----
    {
        const float* wk = WK + kb * 9;  const float* bk = bK + kb * 3;
        const float* wv = WV + vb * 9;  const float* bv = bV + vb * 3;
        #pragma unroll
        for (int it = 0; it < SEQ / TPB_A; ++it) {
            int t = tid + it * TPB_A;
            const float* xk = x + ((size_t)(kb * NB + b) * SEQ + t) * 3;
            float x0 = xk[0], x1 = xk[1], x2 = xk[2];
            Kx[t] = fmaf(wk[0], x0, fmaf(wk[1], x1, fmaf(wk[2], x2, bk[0])));
            Ky[t] = fmaf(wk[3], x0, fmaf(wk[4], x1, fmaf(wk[5], x2, bk[1])));
            Kz[t] = fmaf(wk[6], x0, fmaf(wk[7], x1, fmaf(wk[8], x2, bk[2])));

            const float* xv = x + ((size_t)(vb * NB + b) * SEQ + t) * 3;
            float y0 = xv[0], y1 = xv[1], y2 = xv[2];
            Vx[t] = fmaf(wv[0], y0, fmaf(wv[1], y1, fmaf(wv[2], y2, bv[0])));
            Vy[t] = fmaf(wv[3], y0, fmaf(wv[4], y1, fmaf(wv[5], y2, bv[1])));
            Vz[t] = fmaf(wv[6], y0, fmaf(wv[7], y1, fmaf(wv[8], y2, bv[2])));
        }
    }
    __syncthreads();

    // ---- per-thread Q for rows s0=tid, s1=tid+512; fold log2e/sqrt(3) ----
    const float qscale = 1.4426950408889634f / 1.7320508075688772f;
    ull q0x, q0y, q0z, q1x, q1y, q1z;
    {
        const float* wq = WQ + qb * 9;  const float* bq = bQ + qb * 3;
        const float* xq = x + ((size_t)(qb * NB + b) * SEQ + tid) * 3;
        float x0 = xq[0], x1 = xq[1], x2 = xq[2];
        float a = fmaf(wq[0], x0, fmaf(wq[1], x1, fmaf(wq[2], x2, bq[0]))) * qscale;
        float c = fmaf(wq[3], x0, fmaf(wq[4], x1, fmaf(wq[5], x2, bq[1]))) * qscale;
        float d = fmaf(wq[6], x0, fmaf(wq[7], x1, fmaf(wq[8], x2, bq[2]))) * qscale;
        q0x = pack2(a, a); q0y = pack2(c, c); q0z = pack2(d, d);
        xq = x + ((size_t)(qb * NB + b) * SEQ + tid + TPB_A) * 3;
        x0 = xq[0]; x1 = xq[1]; x2 = xq[2];
        a = fmaf(wq[0], x0, fmaf(wq[1], x1, fmaf(wq[2], x2, bq[0]))) * qscale;
        c = fmaf(wq[3], x0, fmaf(wq[4], x1, fmaf(wq[5], x2, bq[1]))) * qscale;
        d = fmaf(wq[6], x0, fmaf(wq[7], x1, fmaf(wq[8], x2, bq[2]))) * qscale;
        q1x = pack2(a, a); q1y = pack2(c, c); q1z = pack2(d, d);
    }

    const ull* pKx = (const ull*)Kx; const ull* pKy = (const ull*)Ky;
    const ull* pKz = (const ull*)Kz; const ull* pVx = (const ull*)Vx;
    const ull* pVy = (const ull*)Vy; const ull* pVz = (const ull*)Vz;

    ull ax0 = 0, ay0 = 0, az0 = 0, aw0 = 0;
    ull ax1 = 0, ay1 = 0, az1 = 0, aw1 = 0;

    #pragma unroll 4
    for (int t2 = 0; t2 < SEQ / 2; ++t2) {
        ull kx = pKx[t2], ky = pKy[t2], kz = pKz[t2];
        ull vx = pVx[t2], vy = pVy[t2], vz = pVz[t2];

        ull d0 = fma2(q0x, kx, fma2(q0y, ky, mul2(q0z, kz)));
        ull e0 = ex2_2(d0);
        ax0 = fma2(e0, vx, ax0);
        ay0 = fma2(e0, vy, ay0);
        az0 = fma2(e0, vz, az0);
        aw0 = add2(aw0, e0);

        ull d1 = fma2(q1x, kx, fma2(q1y, ky, mul2(q1z, kz)));
        ull e1 = ex2_2(d1);
        ax1 = fma2(e1, vx, ax1);
        ay1 = fma2(e1, vy, ay1);
        az1 = fma2(e1, vz, az1);
        aw1 = add2(aw1, e1);
    }

    // horizontal reduce packed halves
    float l, h;
    unpack2(aw0, l, h); const float inv0 = 1.0f / (l + h);
    unpack2(aw1, l, h); const float inv1 = 1.0f / (l + h);
    unpack2(ax0, l, h); const float o00 = (l + h) * inv0;
    unpack2(ay0, l, h); const float o01 = (l + h) * inv0;
    unpack2(az0, l, h); const float o02 = (l + h) * inv0;
    unpack2(ax1, l, h); const float o10 = (l + h) * inv1;
    unpack2(ay1, l, h); const float o11 = (l + h) * inv1;
    unpack2(az1, l, h); const float o12 = (l + h) * inv1;

    // SoA coalesced store: channel = attn*3 + i
    {
        const size_t r0 = (size_t)b * SEQ + tid;
        const size_t r1 = r0 + TPB_A;
        float* c0 = g_att + (size_t)(attn * 3 + 0) * NROWS;
        float* c1 = g_att + (size_t)(attn * 3 + 1) * NROWS;
        float* c2 = g_att + (size_t)(attn * 3 + 2) * NROWS;
        c0[r0] = o00; c1[r0] = o01; c2[r0] = o02;
        c0[r1] = o10; c1[r1] = o11; c2[r1] = o12;
    }

    // ---- BN partial stats (deterministic block reduction) ----
    float sm[3], sq[3];
    sm[0] = o00 + o10; sm[1] = o01 + o11; sm[2] = o02 + o12;
    sq[0] = o00 * o00 + o10 * o10;
    sq[1] = o01 * o01 + o11 * o11;
    sq[2] = o02 * o02 + o12 * o12;

    #pragma unroll
    for (int off = 16; off > 0; off >>= 1) {
        #pragma unroll
        for (int i = 0; i < 3; ++i) {
            sm[i] += __shfl_down_sync(0xFFFFFFFFu, sm[i], off);
            sq[i] += __shfl_down_sync(0xFFFFFFFFu, sq[i], off);
        }
    }
    const int warp = tid >> 5, lane = tid & 31;
    if (lane == 0) {
        #pragma unroll
        for (int i = 0; i < 3; ++i) {
            sred[warp * 6 + i]     = sm[i];
            sred[warp * 6 + 3 + i] = sq[i];
        }
    }
    __syncthreads();          // also orders this block's g_att stores (hb edge)
    if (tid == 0) {
        float acc[6] = {0.f, 0.f, 0.f, 0.f, 0.f, 0.f};
        #pragma unroll
        for (int w = 0; w < 16; ++w)
            #pragma unroll
            for (int i = 0; i < 6; ++i)
                acc[i] += sred[w * 6 + i];
        #pragma unroll
        for (int i = 0; i < 6; ++i)
            g_part[blk * 6 + i] = acc[i];
        // publish g_att + g_part, then count arrivals
        __threadfence();
        int old = atomicAdd(&g_ctr, 1);
        amlast = (old == NBLK_A - 1);
    }
    __syncthreads();

    // ---- last block finalizes BN stats, then RELEASES all blocks ----
    if (amlast) {
        if (warp < 9) {
            const int w = warp;
            const int at = w / 3, d = w - at * 3;
            float fsm = 0.f, fsq = 0.f;
            for (int i = lane; i < NB; i += 32) {
                const float* p = g_part + (size_t)(at * NB + i) * 6;
                fsm += p[d];
                fsq += p[3 + d];
            }
            #pragma unroll
            for (int off = 16; off > 0; off >>= 1) {
                fsm += __shfl_down_sync(0xFFFFFFFFu, fsm, off);
                fsq += __shfl_down_sync(0xFFFFFFFFu, fsq, off);
            }
            if (lane == 0) {
                const float mean = fsm * (1.0f / NROWS);
                const float var  = fsq * (1.0f / NROWS) - mean * mean;
                const float inv  = rsqrtf(var + 1e-5f);
                const float sc   = gamma[w] * inv;
                g_ss[w]     = sc;
                g_ss[9 + w] = beta[w] - mean * sc;
            }
        }
        __syncthreads();
        if (tid == 0) {
            g_ctr = 0;               // self-reset for next graph replay
            __threadfence();         // publish g_ss (and reset) ...
            atomicAdd(&g_rel, 1);    // ... then release everyone
        }
    }

    // ---- software global barrier: wait for release ----
    if (tid == 0) {
        while (atomicAdd(&g_rel, 0) == s_rel0) { }
        __threadfence();             // acquire: make g_ss/g_att visible
    }
    __syncthreads();

    // ---- fused BN + FC epilogue: blocks 0..95 cover 512 rows each ----
    if (blk < 96) {
        __shared__ float ss[18];
        __shared__ float w[27];
        __shared__ float fb[3];
        if (tid < 18) ss[tid] = g_ss[tid];
        if (tid < 27) w[tid] = fcw[tid];
        if (tid < 3)  fb[tid] = fcb[tid];
        __syncthreads();

        const int row = blk * TPB_A + tid;

        float a[9];
        #pragma unroll
        for (int c = 0; c < 9; ++c)
            a[c] = g_att[(size_t)c * NROWS + row];

        float n[9];
        #pragma unroll
        for (int c = 0; c < 9; ++c)
            n[c] = fmaf(a[c], ss[c], ss[9 + c]);

        float y0 = fb[0], y1 = fb[1], y2 = fb[2];
        #pragma unroll
        for (int c = 0; c < 9; ++c) {
            y0 = fmaf(n[c], w[c], y0);
            y1 = fmaf(n[c], w[9 + c], y1);
            y2 = fmaf(n[c], w[18 + c], y2);
        }
        float* o = out + (size_t)row * 3;
        o[0] = y0; o[1] = y1; o[2] = y2;
    }
}

// ---------------------------------------------------------------------------
extern "C" void kernel_launch(void* const* d_in, const int* in_sizes, int n_in,
                              void* d_out, int out_size)
{
    const float* x     = (const float*)d_in[0];
    const float* WQ    = (const float*)d_in[1];
    const float* bQ    = (const float*)d_in[2];
    const float* WK    = (const float*)d_in[3];
    const float* bK    = (const float*)d_in[4];
    const float* WV    = (const float*)d_in[5];
    const float* bV    = (const float*)d_in[6];
    const float* gamma = (const float*)d_in[7];
    const float* beta  = (const float*)d_in[8];
    const float* fcw   = (const float*)d_in[9];
    const float* fcb   = (const float*)d_in[10];

    attn_kernel<<<NBLK_A, TPB_A>>>(x, WQ, bQ, WK, bK, WV, bV,
                                   gamma, beta, fcw, fcb, (float*)d_out);
}

// round 17
// speedup vs baseline: 1.1823x; 1.0336x over previous
#include <cuda_runtime.h>

#define SEQ 1024
#define NB  48
#define NROWS (NB * SEQ)           // 49152 rows, 9 channels
#define NBLK_A 144                  // 3 attns * 48 batches (single wave!)
#define TPB_A 512

typedef unsigned long long ull;

// scratch (allocation-free rule: __device__ globals)
__device__ float g_att[9 * NROWS];      // SoA: [channel][row]
__device__ float g_part[NBLK_A * 6];    // per-block partial sum/sumsq (3 ch each)
__device__ float g_ss[18];              // BN scale[9], shift[9]
__device__ int   g_ctr = 0;             // arrival counter (self-resetting)
__device__ int   g_rel = 0;             // release epoch (monotonic)

// ---------------- packed f32x2 helpers (Blackwell) ----------------
__device__ __forceinline__ ull pack2(float lo, float hi) {
    ull r; asm("mov.b64 %0, {%1, %2};" : "=l"(r) : "f"(lo), "f"(hi)); return r;
}
__device__ __forceinline__ void unpack2(ull v, float& lo, float& hi) {
    asm("mov.b64 {%0, %1}, %2;" : "=f"(lo), "=f"(hi) : "l"(v));
}
__device__ __forceinline__ ull fma2(ull a, ull b, ull c) {
    ull d; asm("fma.rn.f32x2 %0, %1, %2, %3;" : "=l"(d) : "l"(a), "l"(b), "l"(c)); return d;
}
__device__ __forceinline__ ull mul2(ull a, ull b) {
    ull d; asm("mul.rn.f32x2 %0, %1, %2;" : "=l"(d) : "l"(a), "l"(b)); return d;
}
__device__ __forceinline__ ull add2(ull a, ull b) {
    ull d; asm("add.rn.f32x2 %0, %1, %2;" : "=l"(d) : "l"(a), "l"(b)); return d;
}
__device__ __forceinline__ ull ex2_2(ull d) {
    ull e;
    asm("{\n\t"
        ".reg .f32 dl, dh, el, eh;\n\t"
        "mov.b64 {dl, dh}, %1;\n\t"
        "ex2.approx.f32 el, dl;\n\t"
        "ex2.approx.f32 eh, dh;\n\t"
        "mov.b64 %0, {el, eh};\n\t"
        "}" : "=l"(e) : "l"(d));
    return e;
}

// ---------------------------------------------------------------------------
// SINGLE persistent-wave kernel: projection + cross attention + BN stats
// (threadFenceReduction) + software global barrier + fused BN+FC epilogue
// spread over ALL 144 blocks (1 guarded row per thread).
// 144 blocks <= 148 SMs -> all co-resident -> spin barrier is deadlock-free.
// ---------------------------------------------------------------------------
__global__ __launch_bounds__(TPB_A) void attn_kernel(
    const float* __restrict__ x,
    const float* __restrict__ WQ, const float* __restrict__ bQ,
    const float* __restrict__ WK, const float* __restrict__ bK,
    const float* __restrict__ WV, const float* __restrict__ bV,
    const float* __restrict__ gamma, const float* __restrict__ beta,
    const float* __restrict__ fcw, const float* __restrict__ fcb,
    float* __restrict__ out)
{
    __shared__ __align__(16) float Kx[SEQ], Ky[SEQ], Kz[SEQ];
    __shared__ __align__(16) float Vx[SEQ], Vy[SEQ], Vz[SEQ];
    __shared__ float sred[16 * 6];
    __shared__ int s_rel0;
    __shared__ int amlast;

    const int blk  = blockIdx.x;
    const int attn = blk / NB;
    const int b    = blk - attn * NB;
    const int tid  = threadIdx.x;

    // snapshot release epoch BEFORE contributing (snapshot < release, always)
    if (tid == 0) s_rel0 = atomicAdd(&g_rel, 0);

    // a1=attn(Q2,K0,V1), a2=attn(Q0,K1,V2), a3=attn(Q1,K2,V0)
    const int qmap[3] = {2, 0, 1};
    const int vmap[3] = {1, 2, 0};
    const int qb = qmap[attn], kb = attn, vb = vmap[attn];

    // ---- phase 1: K,V tiles (3x3 projection on the fly) ----
    {
        const float* wk = WK + kb * 9;  const float* bk = bK + kb * 3;
        const float* wv = WV + vb * 9;  const float* bv = bV + vb * 3;
        #pragma unroll
        for (int it = 0; it < SEQ / TPB_A; ++it) {
            int t = tid + it * TPB_A;
            const float* xk = x + ((size_t)(kb * NB + b) * SEQ + t) * 3;
            float x0 = xk[0], x1 = xk[1], x2 = xk[2];
            Kx[t] = fmaf(wk[0], x0, fmaf(wk[1], x1, fmaf(wk[2], x2, bk[0])));
            Ky[t] = fmaf(wk[3], x0, fmaf(wk[4], x1, fmaf(wk[5], x2, bk[1])));
            Kz[t] = fmaf(wk[6], x0, fmaf(wk[7], x1, fmaf(wk[8], x2, bk[2])));

            const float* xv = x + ((size_t)(vb * NB + b) * SEQ + t) * 3;
            float y0 = xv[0], y1 = xv[1], y2 = xv[2];
            Vx[t] = fmaf(wv[0], y0, fmaf(wv[1], y1, fmaf(wv[2], y2, bv[0])));
            Vy[t] = fmaf(wv[3], y0, fmaf(wv[4], y1, fmaf(wv[5], y2, bv[1])));
            Vz[t] = fmaf(wv[6], y0, fmaf(wv[7], y1, fmaf(wv[8], y2, bv[2])));
        }
    }
    __syncthreads();

    // ---- per-thread Q for rows s0=tid, s1=tid+512; fold log2e/sqrt(3) ----
    const float qscale = 1.4426950408889634f / 1.7320508075688772f;
    ull q0x, q0y, q0z, q1x, q1y, q1z;
    {
        const float* wq = WQ + qb * 9;  const float* bq = bQ + qb * 3;
        const float* xq = x + ((size_t)(qb * NB + b) * SEQ + tid) * 3;
        float x0 = xq[0], x1 = xq[1], x2 = xq[2];
        float a = fmaf(wq[0], x0, fmaf(wq[1], x1, fmaf(wq[2], x2, bq[0]))) * qscale;
        float c = fmaf(wq[3], x0, fmaf(wq[4], x1, fmaf(wq[5], x2, bq[1]))) * qscale;
        float d = fmaf(wq[6], x0, fmaf(wq[7], x1, fmaf(wq[8], x2, bq[2]))) * qscale;
        q0x = pack2(a, a); q0y = pack2(c, c); q0z = pack2(d, d);
        xq = x + ((size_t)(qb * NB + b) * SEQ + tid + TPB_A) * 3;
        x0 = xq[0]; x1 = xq[1]; x2 = xq[2];
        a = fmaf(wq[0], x0, fmaf(wq[1], x1, fmaf(wq[2], x2, bq[0]))) * qscale;
        c = fmaf(wq[3], x0, fmaf(wq[4], x1, fmaf(wq[5], x2, bq[1]))) * qscale;
        d = fmaf(wq[6], x0, fmaf(wq[7], x1, fmaf(wq[8], x2, bq[2]))) * qscale;
        q1x = pack2(a, a); q1y = pack2(c, c); q1z = pack2(d, d);
    }

    const ull* pKx = (const ull*)Kx; const ull* pKy = (const ull*)Ky;
    const ull* pKz = (const ull*)Kz; const ull* pVx = (const ull*)Vx;
    const ull* pVy = (const ull*)Vy; const ull* pVz = (const ull*)Vz;

    ull ax0 = 0, ay0 = 0, az0 = 0, aw0 = 0;
    ull ax1 = 0, ay1 = 0, az1 = 0, aw1 = 0;

    #pragma unroll 8
    for (int t2 = 0; t2 < SEQ / 2; ++t2) {
        ull kx = pKx[t2], ky = pKy[t2], kz = pKz[t2];
        ull vx = pVx[t2], vy = pVy[t2], vz = pVz[t2];

        ull d0 = fma2(q0x, kx, fma2(q0y, ky, mul2(q0z, kz)));
        ull e0 = ex2_2(d0);
        ax0 = fma2(e0, vx, ax0);
        ay0 = fma2(e0, vy, ay0);
        az0 = fma2(e0, vz, az0);
        aw0 = add2(aw0, e0);

        ull d1 = fma2(q1x, kx, fma2(q1y, ky, mul2(q1z, kz)));
        ull e1 = ex2_2(d1);
        ax1 = fma2(e1, vx, ax1);
        ay1 = fma2(e1, vy, ay1);
        az1 = fma2(e1, vz, az1);
        aw1 = add2(aw1, e1);
    }

    // horizontal reduce packed halves
    float l, h;
    unpack2(aw0, l, h); const float inv0 = 1.0f / (l + h);
    unpack2(aw1, l, h); const float inv1 = 1.0f / (l + h);
    unpack2(ax0, l, h); const float o00 = (l + h) * inv0;
    unpack2(ay0, l, h); const float o01 = (l + h) * inv0;
    unpack2(az0, l, h); const float o02 = (l + h) * inv0;
    unpack2(ax1, l, h); const float o10 = (l + h) * inv1;
    unpack2(ay1, l, h); const float o11 = (l + h) * inv1;
    unpack2(az1, l, h); const float o12 = (l + h) * inv1;

    // SoA coalesced store: channel = attn*3 + i
    {
        const size_t r0 = (size_t)b * SEQ + tid;
        const size_t r1 = r0 + TPB_A;
        float* c0 = g_att + (size_t)(attn * 3 + 0) * NROWS;
        float* c1 = g_att + (size_t)(attn * 3 + 1) * NROWS;
        float* c2 = g_att + (size_t)(attn * 3 + 2) * NROWS;
        c0[r0] = o00; c1[r0] = o01; c2[r0] = o02;
        c0[r1] = o10; c1[r1] = o11; c2[r1] = o12;
    }

    // ---- BN partial stats (deterministic block reduction) ----
    float sm[3], sq[3];
    sm[0] = o00 + o10; sm[1] = o01 + o11; sm[2] = o02 + o12;
    sq[0] = o00 * o00 + o10 * o10;
    sq[1] = o01 * o01 + o11 * o11;
    sq[2] = o02 * o02 + o12 * o12;

    #pragma unroll
    for (int off = 16; off > 0; off >>= 1) {
        #pragma unroll
        for (int i = 0; i < 3; ++i) {
            sm[i] += __shfl_down_sync(0xFFFFFFFFu, sm[i], off);
            sq[i] += __shfl_down_sync(0xFFFFFFFFu, sq[i], off);
        }
    }
    const int warp = tid >> 5, lane = tid & 31;
    if (lane == 0) {
        #pragma unroll
        for (int i = 0; i < 3; ++i) {
            sred[warp * 6 + i]     = sm[i];
            sred[warp * 6 + 3 + i] = sq[i];
        }
    }
    __syncthreads();          // also orders this block's g_att stores (hb edge)
    if (tid == 0) {
        float acc[6] = {0.f, 0.f, 0.f, 0.f, 0.f, 0.f};
        #pragma unroll
        for (int w = 0; w < 16; ++w)
            #pragma unroll
            for (int i = 0; i < 6; ++i)
                acc[i] += sred[w * 6 + i];
        #pragma unroll
        for (int i = 0; i < 6; ++i)
            g_part[blk * 6 + i] = acc[i];
        // publish g_att + g_part, then count arrivals
        __threadfence();
        int old = atomicAdd(&g_ctr, 1);
        amlast = (old == NBLK_A - 1);
    }
    __syncthreads();

    // ---- last block finalizes BN stats, then RELEASES all blocks ----
    if (amlast) {
        if (warp < 9) {
            const int w = warp;
            const int at = w / 3, d = w - at * 3;
            float fsm = 0.f, fsq = 0.f;
            for (int i = lane; i < NB; i += 32) {
                const float* p = g_part + (size_t)(at * NB + i) * 6;
                fsm += p[d];
                fsq += p[3 + d];
            }
            #pragma unroll
            for (int off = 16; off > 0; off >>= 1) {
                fsm += __shfl_down_sync(0xFFFFFFFFu, fsm, off);
                fsq += __shfl_down_sync(0xFFFFFFFFu, fsq, off);
            }
            if (lane == 0) {
                const float mean = fsm * (1.0f / NROWS);
                const float var  = fsq * (1.0f / NROWS) - mean * mean;
                const float inv  = rsqrtf(var + 1e-5f);
                const float sc   = gamma[w] * inv;
                g_ss[w]     = sc;
                g_ss[9 + w] = beta[w] - mean * sc;
            }
        }
        __syncthreads();
        if (tid == 0) {
            g_ctr = 0;               // self-reset for next graph replay
            __threadfence();         // publish g_ss (and reset) ...
            atomicAdd(&g_rel, 1);    // ... then release everyone
        }
    }

    // ---- software global barrier: wait for release ----
    if (tid == 0) {
        while (atomicAdd(&g_rel, 0) == s_rel0) { }
        __threadfence();             // acquire: make g_ss/g_att visible
    }
    __syncthreads();

    // ---- fused BN + FC epilogue: ALL 144 blocks, 1 guarded row/thread ----
    {
        __shared__ float ss[18];
        __shared__ float w[27];
        __shared__ float fb[3];
        if (tid < 18) ss[tid] = g_ss[tid];
        if (tid < 27) w[tid] = fcw[tid];
        if (tid < 3)  fb[tid] = fcb[tid];
        __syncthreads();

        const int row = blk * TPB_A + tid;    // 73728 slots cover 49152 rows
        if (row < NROWS) {
            float a[9];
            #pragma unroll
            for (int c = 0; c < 9; ++c)
                a[c] = g_att[(size_t)c * NROWS + row];

            float n[9];
            #pragma unroll
            for (int c = 0; c < 9; ++c)
                n[c] = fmaf(a[c], ss[c], ss[9 + c]);

            float y0 = fb[0], y1 = fb[1], y2 = fb[2];
            #pragma unroll
            for (int c = 0; c < 9; ++c) {
                y0 = fmaf(n[c], w[c], y0);
                y1 = fmaf(n[c], w[9 + c], y1);
                y2 = fmaf(n[c], w[18 + c], y2);
            }
            float* o = out + (size_t)row * 3;
            o[0] = y0; o[1] = y1; o[2] = y2;
        }
    }
}

// ---------------------------------------------------------------------------
extern "C" void kernel_launch(void* const* d_in, const int* in_sizes, int n_in,
                              void* d_out, int out_size)
{
    const float* x     = (const float*)d_in[0];
    const float* WQ    = (const float*)d_in[1];
    const float* bQ    = (const float*)d_in[2];
    const float* WK    = (const float*)d_in[3];
    const float* bK    = (const float*)d_in[4];
    const float* WV    = (const float*)d_in[5];
    const float* bV    = (const float*)d_in[6];
    const float* gamma = (const float*)d_in[7];
    const float* beta  = (const float*)d_in[8];
    const float* fcw   = (const float*)d_in[9];
    const float* fcb   = (const float*)d_in[10];

    attn_kernel<<<NBLK_A, TPB_A>>>(x, WQ, bQ, WK, bK, WV, bV,
                                   gamma, beta, fcw, fcb, (float*)d_out);
}